// round 12
// baseline (speedup 1.0000x reference)
#include <cuda_runtime.h>
#include <cuda_fp16.h>
#include <cstdint>

#define D_MODEL 1024
#define D_FF    8192
#define N_ELEM  64
#define D1      128
#define BATCH   2048

__device__ __align__(16) __half g_w1t[(size_t)D_FF * D_MODEL];
__device__ __align__(16) float2 g_rvo[(size_t)BATCH * 136];  // (r, off) + pads
__device__ int g_nact[BATCH];

// ---------------------------------------------------------------------------
// Prep: transpose+convert w1 (d, j, e) fp32 -> g_w1t[(j*64+e)*1024 + d] fp16.
// ---------------------------------------------------------------------------
__global__ __launch_bounds__(256) void prep_kernel(const float* __restrict__ w1) {
    __shared__ float tile[32][65];
    const int t = threadIdx.x;
    const int d0  = (blockIdx.x & 31) * 32;
    const int je0 = (blockIdx.x >> 5) * 64;
    const int dr = t >> 5;
    const int c  = (t & 31) * 2;
#pragma unroll
    for (int r = 0; r < 32; r += 8) {
        float2 v = *reinterpret_cast<const float2*>(
            w1 + (size_t)(d0 + r + dr) * D_FF + je0 + c);
        tile[r + dr][c]     = v.x;
        tile[r + dr][c + 1] = v.y;
    }
    __syncthreads();
    const int jl = t >> 2;
    const int ds = (t & 3) * 8;
    __half tmp[8];
#pragma unroll
    for (int i = 0; i < 8; i++) tmp[i] = __float2half_rn(tile[ds + i][jl]);
    *reinterpret_cast<uint4*>(g_w1t + (size_t)(je0 + jl) * D_MODEL + d0 + ds) =
        *reinterpret_cast<const uint4*>(tmp);
}

// ---------------------------------------------------------------------------
// Kernel A: Phase A + relu + compaction. One CTA per sample, 256 threads.
// Writes compacted (relu, w2 offset) list (+8 zero pads) and nact.
// ---------------------------------------------------------------------------
__global__ __launch_bounds__(256) void phaseA_kernel(
    const int*   __restrict__ qmask,
    const float* __restrict__ x,
    float*       __restrict__ out_mask)
{
    __shared__ __align__(16) __half x_h[D_MODEL];
    __shared__ float  midr[D1];
    __shared__ int    ms[D1];
    __shared__ float2 rvo[D1 + 8];
    __shared__ int    wcnt[4];

    const int b = blockIdx.x;
    const int t = threadIdx.x;
    const int w = t >> 5;
    const int l = t & 31;

    {
        float4 v = reinterpret_cast<const float4*>(x + (size_t)b * D_MODEL)[t];
        __half2 h0 = __floats2half2_rn(v.x, v.y);
        __half2 h1 = __floats2half2_rn(v.z, v.w);
        uint2 u;
        u.x = *reinterpret_cast<unsigned*>(&h0);
        u.y = *reinterpret_cast<unsigned*>(&h1);
        *reinterpret_cast<uint2*>(x_h + t * 4) = u;
    }
    if (t < D1) {
        int m = qmask[(size_t)b * D1 + t];
        ms[t] = m;
        if (out_mask) out_mask[(size_t)b * D1 + t] = (float)m;
    }
    __syncthreads();

    // ---- Phase A: batched dual-column loads + interleaved HFMA2 chains ----
    {
        const uint4* xh4 = reinterpret_cast<const uint4*>(x_h);
        const uint4 xv0 = xh4[l], xv1 = xh4[l + 32], xv2 = xh4[l + 64], xv3 = xh4[l + 96];
        const __half2* xA = reinterpret_cast<const __half2*>(&xv0);
        const __half2* xB = reinterpret_cast<const __half2*>(&xv1);
        const __half2* xC = reinterpret_cast<const __half2*>(&xv2);
        const __half2* xD = reinterpret_cast<const __half2*>(&xv3);

#pragma unroll
        for (int p = 0; p < 8; p++) {
            const int jA = w * 16 + p;
            const int jB = jA + 8;
            const uint4* cpA = reinterpret_cast<const uint4*>(
                g_w1t + (((size_t)jA * N_ELEM + ms[jA]) << 10));
            const uint4* cpB = reinterpret_cast<const uint4*>(
                g_w1t + (((size_t)jB * N_ELEM + ms[jB]) << 10));

            uint4 ua0 = cpA[l], ua1 = cpA[l + 32], ua2 = cpA[l + 64], ua3 = cpA[l + 96];
            uint4 ub0 = cpB[l], ub1 = cpB[l + 32], ub2 = cpB[l + 64], ub3 = cpB[l + 96];

            const __half2* cA0 = reinterpret_cast<const __half2*>(&ua0);
            const __half2* cA1 = reinterpret_cast<const __half2*>(&ua1);
            const __half2* cA2 = reinterpret_cast<const __half2*>(&ua2);
            const __half2* cA3 = reinterpret_cast<const __half2*>(&ua3);
            const __half2* cB0 = reinterpret_cast<const __half2*>(&ub0);
            const __half2* cB1 = reinterpret_cast<const __half2*>(&ub1);
            const __half2* cB2 = reinterpret_cast<const __half2*>(&ub2);
            const __half2* cB3 = reinterpret_cast<const __half2*>(&ub3);

            __half2 a0 = __hmul2(cA0[0], xA[0]);
            __half2 e0 = __hmul2(cB0[0], xA[0]);
            __half2 a1 = __hmul2(cA0[1], xA[1]);
            __half2 e1 = __hmul2(cB0[1], xA[1]);
            __half2 a2 = __hmul2(cA0[2], xA[2]);
            __half2 e2 = __hmul2(cB0[2], xA[2]);
            __half2 a3 = __hmul2(cA0[3], xA[3]);
            __half2 e3 = __hmul2(cB0[3], xA[3]);

            a0 = __hfma2(cA1[0], xB[0], a0);
            e0 = __hfma2(cB1[0], xB[0], e0);
            a1 = __hfma2(cA1[1], xB[1], a1);
            e1 = __hfma2(cB1[1], xB[1], e1);
            a2 = __hfma2(cA1[2], xB[2], a2);
            e2 = __hfma2(cB1[2], xB[2], e2);
            a3 = __hfma2(cA1[3], xB[3], a3);
            e3 = __hfma2(cB1[3], xB[3], e3);

            a0 = __hfma2(cA2[0], xC[0], a0);
            e0 = __hfma2(cB2[0], xC[0], e0);
            a1 = __hfma2(cA2[1], xC[1], a1);
            e1 = __hfma2(cB2[1], xC[1], e1);
            a2 = __hfma2(cA2[2], xC[2], a2);
            e2 = __hfma2(cB2[2], xC[2], e2);
            a3 = __hfma2(cA2[3], xC[3], a3);
            e3 = __hfma2(cB2[3], xC[3], e3);

            a0 = __hfma2(cA3[0], xD[0], a0);
            e0 = __hfma2(cB3[0], xD[0], e0);
            a1 = __hfma2(cA3[1], xD[1], a1);
            e1 = __hfma2(cB3[1], xD[1], e1);
            a2 = __hfma2(cA3[2], xD[2], a2);
            e2 = __hfma2(cB3[2], xD[2], e2);
            a3 = __hfma2(cA3[3], xD[3], a3);
            e3 = __hfma2(cB3[3], xD[3], e3);

            float2 fa0 = __half22float2(a0);
            float2 fa1 = __half22float2(a1);
            float2 fa2 = __half22float2(a2);
            float2 fa3 = __half22float2(a3);
            float sA = ((fa0.x + fa0.y) + (fa1.x + fa1.y)) +
                       ((fa2.x + fa2.y) + (fa3.x + fa3.y));
            float2 fe0 = __half22float2(e0);
            float2 fe1 = __half22float2(e1);
            float2 fe2 = __half22float2(e2);
            float2 fe3 = __half22float2(e3);
            float sB = ((fe0.x + fe0.y) + (fe1.x + fe1.y)) +
                       ((fe2.x + fe2.y) + (fe3.x + fe3.y));

            float v   = (l & 1) ? sB : sA;
            float oth = (l & 1) ? sA : sB;
            v += __shfl_xor_sync(0xffffffffu, oth, 1);
            v += __shfl_xor_sync(0xffffffffu, v, 2);
            v += __shfl_xor_sync(0xffffffffu, v, 4);
            v += __shfl_xor_sync(0xffffffffu, v, 8);
            v += __shfl_xor_sync(0xffffffffu, v, 16);
            if (l < 2) midr[(l == 0) ? jA : jB] = fmaxf(v, 0.f);
        }
    }
    __syncthreads();

    // ---- Compaction (deterministic, ordered by j) ----
    float cr = 0.f; bool act = false; int widx = 0;
    if (t < D1) {
        cr = midr[t];
        act = cr > 0.f;
        unsigned mb = __ballot_sync(0xffffffffu, act);
        widx = __popc(mb & ((1u << l) - 1u));
        if (l == 0) wcnt[w] = __popc(mb);
    }
    __syncthreads();
    const int nact = wcnt[0] + wcnt[1] + wcnt[2] + wcnt[3];
    if (act) {
        int base = 0;
#pragma unroll
        for (int q = 0; q < 3; q++) if (w > q) base += wcnt[q];
        const int off = (ms[t] * D1 + t) << 10;
        rvo[base + widx] = make_float2(cr, __int_as_float(off));
    }
    if (t < 8) rvo[nact + t] = make_float2(0.f, __int_as_float(0));
    __syncthreads();

    // write compacted list + count
    {
        float2* gdst = g_rvo + (size_t)b * 136;
        const int ntot = nact + 8;
        if (t < ntot) gdst[t] = rvo[t];
        if (t == 0) g_nact[b] = nact;
    }
}

// ---------------------------------------------------------------------------
// Kernel B: one CTA per sample, 256 threads, ~28 regs -> 8 CTAs/SM.
// Reads compacted list into smem, pair loop with 2-ahead prefetch,
// dual f32x2 accumulator chains; thread owns 4 outputs.
// ---------------------------------------------------------------------------
__global__ __launch_bounds__(256) void phaseB_kernel(
    const float* __restrict__ w2,
    const float* __restrict__ b2,
    float*       __restrict__ out_res)
{
    __shared__ float2 rvo[D1 + 8];

    const int b = blockIdx.x;
    const int t = threadIdx.x;
    const int nact = g_nact[b];
    const int ntot = nact + 8;

    {
        const float2* gsrc = g_rvo + (size_t)b * 136;
        if (t < ntot) rvo[t] = gsrc[t];
    }
    __syncthreads();

    const int dbase = t * 4;
    unsigned long long a01a = 0ull, a23a = 0ull;
    unsigned long long a01b = 0ull, a23b = 0ull;

#define B_STEP(q, A01, A23)                                                    \
    {                                                                          \
        const float r = (q).x;                                                 \
        const int  off = __float_as_int((q).y);                                \
        float4 wv = *reinterpret_cast<const float4*>(w2 + off + dbase);        \
        unsigned long long w01, w23, rp;                                       \
        unsigned ru = __float_as_uint(r);                                      \
        asm("mov.b64 %0, {%1, %1};" : "=l"(rp) : "r"(ru));                     \
        w01 = *reinterpret_cast<unsigned long long*>(&wv.x);                   \
        w23 = *reinterpret_cast<unsigned long long*>(&wv.z);                   \
        asm("fma.rn.f32x2 %0, %1, %2, %3;"                                     \
            : "=l"(A01) : "l"(w01), "l"(rp), "l"(A01));                        \
        asm("fma.rn.f32x2 %0, %1, %2, %3;"                                     \
            : "=l"(A23) : "l"(w23), "l"(rp), "l"(A23));                        \
    }

    float2 q0 = rvo[0];
    float2 q1 = rvo[1];
    for (int k = 0; k < nact; k += 2) {
        float2 n0 = rvo[k + 2];
        float2 n1 = rvo[k + 3];
        B_STEP(q0, a01a, a23a);
        B_STEP(q1, a01b, a23b);
        q0 = n0; q1 = n1;
    }
#undef B_STEP

    unsigned long long acc01, acc23;
    asm("add.rn.f32x2 %0, %1, %2;" : "=l"(acc01) : "l"(a01a), "l"(a01b));
    asm("add.rn.f32x2 %0, %1, %2;" : "=l"(acc23) : "l"(a23a), "l"(a23b));

    float4 bv = reinterpret_cast<const float4*>(b2)[t];
    unsigned r0, r1, r2, r3;
    asm("mov.b64 {%0, %1}, %2;" : "=r"(r0), "=r"(r1) : "l"(acc01));
    asm("mov.b64 {%0, %1}, %2;" : "=r"(r2), "=r"(r3) : "l"(acc23));
    float4 o;
    o.x = __uint_as_float(r0) + bv.x;
    o.y = __uint_as_float(r1) + bv.y;
    o.z = __uint_as_float(r2) + bv.z;
    o.w = __uint_as_float(r3) + bv.w;
    reinterpret_cast<float4*>(out_res + (size_t)b * D_MODEL)[t] = o;
}

// ---------------------------------------------------------------------------
extern "C" void kernel_launch(void* const* d_in, const int* in_sizes, int n_in,
                              void* d_out, int out_size) {
    const int*   qmask = nullptr;
    const float* x = nullptr, *w1 = nullptr, *w2 = nullptr, *b2 = nullptr;
    for (int i = 0; i < n_in; i++) {
        const int sz = in_sizes[i];
        if (sz == BATCH * D1)            qmask = (const int*)d_in[i];
        else if (sz == BATCH * D_MODEL)  x     = (const float*)d_in[i];
        else if (sz == D_MODEL)          b2    = (const float*)d_in[i];
        else if (sz == D_MODEL * D_FF) {
            if (!w1) w1 = (const float*)d_in[i];
            else     w2 = (const float*)d_in[i];
        }
    }

    float* out      = (float*)d_out;
    float* out_mask = nullptr;
    float* out_res  = out;
    if (out_size >= BATCH * D1 + BATCH * D_MODEL) {
        out_mask = out;
        out_res  = out + BATCH * D1;
    }

    prep_kernel<<<4096, 256>>>(w1);
    phaseA_kernel<<<BATCH, 256>>>(qmask, x, out_mask);
    phaseB_kernel<<<BATCH, 256>>>(w2, b2, out_res);
}

// round 13
// speedup vs baseline: 1.5458x; 1.5458x over previous
#include <cuda_runtime.h>
#include <cuda_fp16.h>
#include <cstdint>

#define D_MODEL 1024
#define D_FF    8192
#define N_ELEM  64
#define D1      128
#define BATCH   2048

__device__ __align__(16) __half g_w1t[(size_t)D_FF * D_MODEL];
__device__ __align__(16) __half g_w2h[(size_t)D_FF * D_MODEL];

// ---------------------------------------------------------------------------
// Prep (merged): blocks [0,4096) transpose+convert w1; [4096,8192) convert w2.
// ---------------------------------------------------------------------------
__global__ __launch_bounds__(256) void prep_kernel(const float* __restrict__ w1,
                                                   const float* __restrict__ w2) {
    __shared__ float tile[32][65];
    const int t = threadIdx.x;
    if (blockIdx.x >= 4096) {
        const size_t i = ((size_t)(blockIdx.x - 4096) * 256 + t) * 8;
        float4 a = *reinterpret_cast<const float4*>(w2 + i);
        float4 b = *reinterpret_cast<const float4*>(w2 + i + 4);
        __half tmp[8];
        tmp[0] = __float2half_rn(a.x); tmp[1] = __float2half_rn(a.y);
        tmp[2] = __float2half_rn(a.z); tmp[3] = __float2half_rn(a.w);
        tmp[4] = __float2half_rn(b.x); tmp[5] = __float2half_rn(b.y);
        tmp[6] = __float2half_rn(b.z); tmp[7] = __float2half_rn(b.w);
        *reinterpret_cast<uint4*>(g_w2h + i) = *reinterpret_cast<const uint4*>(tmp);
        return;
    }
    const int d0  = (blockIdx.x & 31) * 32;
    const int je0 = (blockIdx.x >> 5) * 64;
    const int dr = t >> 5;
    const int c  = (t & 31) * 2;
#pragma unroll
    for (int r = 0; r < 32; r += 8) {
        float2 v = *reinterpret_cast<const float2*>(
            w1 + (size_t)(d0 + r + dr) * D_FF + je0 + c);
        tile[r + dr][c]     = v.x;
        tile[r + dr][c + 1] = v.y;
    }
    __syncthreads();
    const int jl = t >> 2;
    const int ds = (t & 3) * 8;
    __half tmp[8];
#pragma unroll
    for (int i = 0; i < 8; i++) tmp[i] = __float2half_rn(tile[ds + i][jl]);
    *reinterpret_cast<uint4*>(g_w1t + (size_t)(je0 + jl) * D_MODEL + d0 + ds) =
        *reinterpret_cast<const uint4*>(tmp);
}

// ---------------------------------------------------------------------------
// Fused main kernel: one CTA per sample, 256 threads (8 warps). R9 structure.
// Phase A: warp w computes j = w*16..w*16+15 in pairs; 8 batched LDG.128 +
//   interleaved dual HFMA2 chains; dual-butterfly reduction.
// Compaction: ballot-scan active-j list, zero-padded by 8 entries.
// Phase B: fp16 w2 (LDG.64 per j -> HALF the L1tex wavefronts), cvt to fp32,
//   dual f32x2 accumulator chains; thread owns 4 outputs.
// ---------------------------------------------------------------------------
__global__ __launch_bounds__(256) void fused_kernel(
    const int*   __restrict__ qmask,
    const float* __restrict__ x,
    const float* __restrict__ b2,
    float*       __restrict__ out_res,
    float*       __restrict__ out_mask)
{
    __shared__ __align__(16) __half x_h[D_MODEL];   // 2 KB
    __shared__ float  midr[D1];
    __shared__ int    ms[D1];
    __shared__ float2 rvo[D1 + 8];                   // (relu, w2h offset) + pads
    __shared__ int    wcnt[4];

    const int b = blockIdx.x;
    const int t = threadIdx.x;
    const int w = t >> 5;
    const int l = t & 31;

    // stage x as fp16 + masks
    {
        float4 v = reinterpret_cast<const float4*>(x + (size_t)b * D_MODEL)[t];
        __half2 h0 = __floats2half2_rn(v.x, v.y);
        __half2 h1 = __floats2half2_rn(v.z, v.w);
        uint2 u;
        u.x = *reinterpret_cast<unsigned*>(&h0);
        u.y = *reinterpret_cast<unsigned*>(&h1);
        *reinterpret_cast<uint2*>(x_h + t * 4) = u;
    }
    if (t < D1) {
        int m = qmask[(size_t)b * D1 + t];
        ms[t] = m;
        if (out_mask) out_mask[(size_t)b * D1 + t] = (float)m;
    }
    __syncthreads();

    // ---- Phase A ----
    {
        const uint4* xh4 = reinterpret_cast<const uint4*>(x_h);
        const uint4 xv0 = xh4[l], xv1 = xh4[l + 32], xv2 = xh4[l + 64], xv3 = xh4[l + 96];
        const __half2* xA = reinterpret_cast<const __half2*>(&xv0);
        const __half2* xB = reinterpret_cast<const __half2*>(&xv1);
        const __half2* xC = reinterpret_cast<const __half2*>(&xv2);
        const __half2* xD = reinterpret_cast<const __half2*>(&xv3);

#pragma unroll
        for (int p = 0; p < 8; p++) {
            const int jA = w * 16 + p;
            const int jB = jA + 8;
            const uint4* cpA = reinterpret_cast<const uint4*>(
                g_w1t + (((size_t)jA * N_ELEM + ms[jA]) << 10));
            const uint4* cpB = reinterpret_cast<const uint4*>(
                g_w1t + (((size_t)jB * N_ELEM + ms[jB]) << 10));

            uint4 ua0 = cpA[l], ua1 = cpA[l + 32], ua2 = cpA[l + 64], ua3 = cpA[l + 96];
            uint4 ub0 = cpB[l], ub1 = cpB[l + 32], ub2 = cpB[l + 64], ub3 = cpB[l + 96];

            const __half2* cA0 = reinterpret_cast<const __half2*>(&ua0);
            const __half2* cA1 = reinterpret_cast<const __half2*>(&ua1);
            const __half2* cA2 = reinterpret_cast<const __half2*>(&ua2);
            const __half2* cA3 = reinterpret_cast<const __half2*>(&ua3);
            const __half2* cB0 = reinterpret_cast<const __half2*>(&ub0);
            const __half2* cB1 = reinterpret_cast<const __half2*>(&ub1);
            const __half2* cB2 = reinterpret_cast<const __half2*>(&ub2);
            const __half2* cB3 = reinterpret_cast<const __half2*>(&ub3);

            __half2 a0 = __hmul2(cA0[0], xA[0]);
            __half2 e0 = __hmul2(cB0[0], xA[0]);
            __half2 a1 = __hmul2(cA0[1], xA[1]);
            __half2 e1 = __hmul2(cB0[1], xA[1]);
            __half2 a2 = __hmul2(cA0[2], xA[2]);
            __half2 e2 = __hmul2(cB0[2], xA[2]);
            __half2 a3 = __hmul2(cA0[3], xA[3]);
            __half2 e3 = __hmul2(cB0[3], xA[3]);

            a0 = __hfma2(cA1[0], xB[0], a0);
            e0 = __hfma2(cB1[0], xB[0], e0);
            a1 = __hfma2(cA1[1], xB[1], a1);
            e1 = __hfma2(cB1[1], xB[1], e1);
            a2 = __hfma2(cA1[2], xB[2], a2);
            e2 = __hfma2(cB1[2], xB[2], e2);
            a3 = __hfma2(cA1[3], xB[3], a3);
            e3 = __hfma2(cB1[3], xB[3], e3);

            a0 = __hfma2(cA2[0], xC[0], a0);
            e0 = __hfma2(cB2[0], xC[0], e0);
            a1 = __hfma2(cA2[1], xC[1], a1);
            e1 = __hfma2(cB2[1], xC[1], e1);
            a2 = __hfma2(cA2[2], xC[2], a2);
            e2 = __hfma2(cB2[2], xC[2], e2);
            a3 = __hfma2(cA2[3], xC[3], a3);
            e3 = __hfma2(cB2[3], xC[3], e3);

            a0 = __hfma2(cA3[0], xD[0], a0);
            e0 = __hfma2(cB3[0], xD[0], e0);
            a1 = __hfma2(cA3[1], xD[1], a1);
            e1 = __hfma2(cB3[1], xD[1], e1);
            a2 = __hfma2(cA3[2], xD[2], a2);
            e2 = __hfma2(cB3[2], xD[2], e2);
            a3 = __hfma2(cA3[3], xD[3], a3);
            e3 = __hfma2(cB3[3], xD[3], e3);

            float2 fa0 = __half22float2(a0);
            float2 fa1 = __half22float2(a1);
            float2 fa2 = __half22float2(a2);
            float2 fa3 = __half22float2(a3);
            float sA = ((fa0.x + fa0.y) + (fa1.x + fa1.y)) +
                       ((fa2.x + fa2.y) + (fa3.x + fa3.y));
            float2 fe0 = __half22float2(e0);
            float2 fe1 = __half22float2(e1);
            float2 fe2 = __half22float2(e2);
            float2 fe3 = __half22float2(e3);
            float sB = ((fe0.x + fe0.y) + (fe1.x + fe1.y)) +
                       ((fe2.x + fe2.y) + (fe3.x + fe3.y));

            float v   = (l & 1) ? sB : sA;
            float oth = (l & 1) ? sA : sB;
            v += __shfl_xor_sync(0xffffffffu, oth, 1);
            v += __shfl_xor_sync(0xffffffffu, v, 2);
            v += __shfl_xor_sync(0xffffffffu, v, 4);
            v += __shfl_xor_sync(0xffffffffu, v, 8);
            v += __shfl_xor_sync(0xffffffffu, v, 16);
            if (l < 2) midr[(l == 0) ? jA : jB] = fmaxf(v, 0.f);
        }
    }
    __syncthreads();

    // ---- Compaction (deterministic, ordered by j) ----
    {
        float cr = 0.f; bool act = false; int widx = 0;
        if (t < D1) {
            cr = midr[t];
            act = cr > 0.f;
            unsigned mb = __ballot_sync(0xffffffffu, act);
            widx = __popc(mb & ((1u << l) - 1u));
            if (l == 0) wcnt[w] = __popc(mb);
        }
        __syncthreads();
        if (act) {
            int base = 0;
#pragma unroll
            for (int q = 0; q < 3; q++) if (w > q) base += wcnt[q];
            const int off = (ms[t] * D1 + t) << 10;   // element offset into w2h
            rvo[base + widx] = make_float2(cr, __int_as_float(off));
        }
        __syncthreads();
    }
    const int nact = wcnt[0] + wcnt[1] + wcnt[2] + wcnt[3];
    if (t < 8) rvo[nact + t] = make_float2(0.f, __int_as_float(0));
    __syncthreads();

    // ---- Phase B: fp16 w2, fp32 accumulate, dual chains ----
    {
        const int dbase = t * 4;
        unsigned long long a01a = 0ull, a23a = 0ull;
        unsigned long long a01b = 0ull, a23b = 0ull;

#define B_STEP(q, A01, A23)                                                    \
        {                                                                      \
            const float r = (q).x;                                             \
            const int  off = __float_as_int((q).y);                            \
            uint2 hv = *reinterpret_cast<const uint2*>(g_w2h + off + dbase);   \
            __half2 h0 = *reinterpret_cast<const __half2*>(&hv.x);             \
            __half2 h1 = *reinterpret_cast<const __half2*>(&hv.y);             \
            float2 f0 = __half22float2(h0);                                    \
            float2 f1 = __half22float2(h1);                                    \
            unsigned long long w01, w23, rp;                                   \
            unsigned ru = __float_as_uint(r);                                  \
            asm("mov.b64 %0, {%1, %1};" : "=l"(rp) : "r"(ru));                 \
            asm("mov.b64 %0, {%1, %2};" : "=l"(w01) : "f"(f0.x), "f"(f0.y));   \
            asm("mov.b64 %0, {%1, %2};" : "=l"(w23) : "f"(f1.x), "f"(f1.y));   \
            asm("fma.rn.f32x2 %0, %1, %2, %3;"                                 \
                : "=l"(A01) : "l"(w01), "l"(rp), "l"(A01));                    \
            asm("fma.rn.f32x2 %0, %1, %2, %3;"                                 \
                : "=l"(A23) : "l"(w23), "l"(rp), "l"(A23));                    \
        }

        float2 q0 = rvo[0];
        float2 q1 = rvo[1];
        for (int k = 0; k < nact; k += 2) {
            float2 n0 = rvo[k + 2];
            float2 n1 = rvo[k + 3];
            B_STEP(q0, a01a, a23a);
            B_STEP(q1, a01b, a23b);
            q0 = n0; q1 = n1;
        }
#undef B_STEP

        unsigned long long acc01, acc23;
        asm("add.rn.f32x2 %0, %1, %2;" : "=l"(acc01) : "l"(a01a), "l"(a01b));
        asm("add.rn.f32x2 %0, %1, %2;" : "=l"(acc23) : "l"(a23a), "l"(a23b));

        float4 bv = reinterpret_cast<const float4*>(b2)[t];
        unsigned r0, r1, r2, r3;
        asm("mov.b64 {%0, %1}, %2;" : "=r"(r0), "=r"(r1) : "l"(acc01));
        asm("mov.b64 {%0, %1}, %2;" : "=r"(r2), "=r"(r3) : "l"(acc23));
        float4 o;
        o.x = __uint_as_float(r0) + bv.x;
        o.y = __uint_as_float(r1) + bv.y;
        o.z = __uint_as_float(r2) + bv.z;
        o.w = __uint_as_float(r3) + bv.w;
        reinterpret_cast<float4*>(out_res + (size_t)b * D_MODEL)[t] = o;
    }
}

// ---------------------------------------------------------------------------
extern "C" void kernel_launch(void* const* d_in, const int* in_sizes, int n_in,
                              void* d_out, int out_size) {
    const int*   qmask = nullptr;
    const float* x = nullptr, *w1 = nullptr, *w2 = nullptr, *b2 = nullptr;
    for (int i = 0; i < n_in; i++) {
        const int sz = in_sizes[i];
        if (sz == BATCH * D1)            qmask = (const int*)d_in[i];
        else if (sz == BATCH * D_MODEL)  x     = (const float*)d_in[i];
        else if (sz == D_MODEL)          b2    = (const float*)d_in[i];
        else if (sz == D_MODEL * D_FF) {
            if (!w1) w1 = (const float*)d_in[i];
            else     w2 = (const float*)d_in[i];
        }
    }

    float* out      = (float*)d_out;
    float* out_mask = nullptr;
    float* out_res  = out;
    if (out_size >= BATCH * D1 + BATCH * D_MODEL) {
        out_mask = out;
        out_res  = out + BATCH * D1;
    }

    prep_kernel<<<8192, 256>>>(w1, w2);
    fused_kernel<<<BATCH, 256>>>(qmask, x, b2, out_res, out_mask);
}